// round 7
// baseline (speedup 1.0000x reference)
#include <cuda_runtime.h>

#define NN 100000
#define EE 1600000
#define CC 16
#define HH 32
#define NLAY 8
#define TPB 256
#define MTPB 128
#define MAXIT 10
#define THRESH 5000   // count <= 5000  <=>  ratio <= 0.05 (exact in fp32)
#define FGRID 592     // 4 blocks/SM x 148 SMs, guaranteed co-resident
#define FTPB 256

// ---------------- device scratch ----------------
__device__ unsigned int        g_mkey[NN];
__device__ double              g_ssum[NN];
__device__ float               g_tmp[EE];
__device__ float               g_score[EE];
__device__ unsigned long long  g_packs[NN];
__device__ unsigned long long  g_packd[NN];
__device__ int                 g_maxidx[NN];
__device__ int                 g_part[NN];
__device__ unsigned char       g_nrem[NN];
__device__ unsigned char       g_rm[NN];
__device__ int                 g_cnt[MAXIT];
__device__ int                 g_lc[2];
__device__ int4                g_list[2][EE];
__device__ float               g_P[NN * HH];   // x @ W0[:16] + b0  (src half)
__device__ float               g_Q[NN * HH];   // x @ W0[16:]       (dst half)
__device__ unsigned int        g_arrive;       // grid barrier counter

__device__ __forceinline__ unsigned int fkey(float f) {
    unsigned int b = __float_as_uint(f);
    return (b & 0x80000000u) ? ~b : (b | 0x80000000u);
}
__device__ __forceinline__ float fkey_inv(unsigned int k) {
    unsigned int b = (k & 0x80000000u) ? (k ^ 0x80000000u) : ~k;
    return __uint_as_float(b);
}
__device__ __forceinline__ bool iter_done(int t) {
    return (t > 0) && (g_cnt[t - 1] <= THRESH);
}

// software grid barrier: monotonic arrival counter, release/acquire ordered
__device__ __forceinline__ void gbar(unsigned int target) {
    __syncthreads();
    if (threadIdx.x == 0) {
        asm volatile("fence.acq_rel.gpu;" ::: "memory");
        atomicAdd(&g_arrive, 1u);
        unsigned int v;
        do {
            asm volatile("ld.acquire.gpu.u32 %0, [%1];"
                         : "=r"(v) : "l"(&g_arrive) : "memory");
            if (v < target) __nanosleep(128);
        } while (v < target);
    }
    __syncthreads();
}

// ---------------- layer-1 per-node precompute + global init (fused) ----------------
__global__ void __launch_bounds__(TPB)
k_pre(const float* __restrict__ x, const float* __restrict__ Wh,
      const float* __restrict__ bh) {
    __shared__ __align__(16) float W0[HH * HH];
    __shared__ float b0[HH];
    for (int i = threadIdx.x; i < HH * HH; i += blockDim.x) W0[i] = Wh[i];
    if (threadIdx.x < HH) b0[threadIdx.x] = bh[threadIdx.x];
    __syncthreads();

    int n = blockIdx.x * blockDim.x + threadIdx.x;

    if (n < NN) {
        g_mkey[n] = 0u;
        g_ssum[n] = 0.0;
        g_packs[n] = 0ull;       // score=0.0f, eid=E (matches empty-segment fill)
        g_packd[n] = 0ull;
        g_nrem[n] = 1;
        g_rm[n] = 0;
        g_part[n] = -1;
    }
    if (n < MAXIT) g_cnt[n] = 0;
    if (n < 2) g_lc[n] = 0;
    if (n == 0) g_arrive = 0u;

    if (n >= NN) return;

    float xv[CC];
    const float4* xp = (const float4*)(x + (size_t)n * CC);
#pragma unroll
    for (int q = 0; q < 4; q++) {
        float4 v = xp[q];
        xv[4 * q] = v.x; xv[4 * q + 1] = v.y; xv[4 * q + 2] = v.z; xv[4 * q + 3] = v.w;
    }
    float a[HH];
#pragma unroll
    for (int j = 0; j < HH; j++) a[j] = b0[j];
#pragma unroll
    for (int k = 0; k < CC; k++) {
        float xk = xv[k];
        const float4* w4 = (const float4*)(W0 + k * HH);
#pragma unroll
        for (int j = 0; j < HH / 4; j++) {
            float4 w = w4[j];
            a[4 * j] = fmaf(xk, w.x, a[4 * j]);
            a[4 * j + 1] = fmaf(xk, w.y, a[4 * j + 1]);
            a[4 * j + 2] = fmaf(xk, w.z, a[4 * j + 2]);
            a[4 * j + 3] = fmaf(xk, w.w, a[4 * j + 3]);
        }
    }
    float4* Pp = (float4*)(g_P + (size_t)n * HH);
#pragma unroll
    for (int j = 0; j < HH / 4; j++)
        Pp[j] = make_float4(a[4 * j], a[4 * j + 1], a[4 * j + 2], a[4 * j + 3]);

#pragma unroll
    for (int j = 0; j < HH; j++) a[j] = 0.0f;
#pragma unroll
    for (int k = 0; k < CC; k++) {
        float xk = xv[k];
        const float4* w4 = (const float4*)(W0 + (CC + k) * HH);
#pragma unroll
        for (int j = 0; j < HH / 4; j++) {
            float4 w = w4[j];
            a[4 * j] = fmaf(xk, w.x, a[4 * j]);
            a[4 * j + 1] = fmaf(xk, w.y, a[4 * j + 1]);
            a[4 * j + 2] = fmaf(xk, w.z, a[4 * j + 2]);
            a[4 * j + 3] = fmaf(xk, w.w, a[4 * j + 3]);
        }
    }
    float4* Qp = (float4*)(g_Q + (size_t)n * HH);
#pragma unroll
    for (int j = 0; j < HH / 4; j++)
        Qp[j] = make_float4(a[4 * j], a[4 * j + 1], a[4 * j + 2], a[4 * j + 3]);
}

// ---------------- edge MLP layers 2..8, 2 edges per thread (bit-exact) ----------------
__global__ void __launch_bounds__(MTPB)
k_mlp(const int* __restrict__ ei,
      const float* __restrict__ Wh, const float* __restrict__ bh,
      const float* __restrict__ Wo, const float* __restrict__ bo) {
    __shared__ __align__(16) float Wsh[(NLAY - 1) * HH * HH];
    __shared__ float bsh[(NLAY - 1) * HH];
    __shared__ float Wosh[HH];
    __shared__ float bosh;
    for (int i = threadIdx.x; i < (NLAY - 1) * HH * HH; i += blockDim.x)
        Wsh[i] = Wh[HH * HH + i];
    for (int i = threadIdx.x; i < (NLAY - 1) * HH; i += blockDim.x)
        bsh[i] = bh[HH + i];
    if (threadIdx.x < HH) Wosh[threadIdx.x] = Wo[threadIdx.x];
    if (threadIdx.x == 0) bosh = bo[0];
    __syncthreads();

    int i = blockIdx.x * MTPB + threadIdx.x;
    int eA = i;
    int eB = i + (EE / 2);
    int sA = ei[eA], dA = ei[EE + eA];
    int sB = ei[eB], dB = ei[EE + eB];

    float h[2][HH];
    {
        const float4* PA = (const float4*)(g_P + (size_t)sA * HH);
        const float4* QA = (const float4*)(g_Q + (size_t)dA * HH);
        const float4* PB = (const float4*)(g_P + (size_t)sB * HH);
        const float4* QB = (const float4*)(g_Q + (size_t)dB * HH);
#pragma unroll
        for (int q = 0; q < HH / 4; q++) {
            float4 pa = PA[q], qa = QA[q];
            float4 pb = PB[q], qb = QB[q];
            h[0][4 * q + 0] = fmaxf(pa.x + qa.x, 0.0f);
            h[0][4 * q + 1] = fmaxf(pa.y + qa.y, 0.0f);
            h[0][4 * q + 2] = fmaxf(pa.z + qa.z, 0.0f);
            h[0][4 * q + 3] = fmaxf(pa.w + qa.w, 0.0f);
            h[1][4 * q + 0] = fmaxf(pb.x + qb.x, 0.0f);
            h[1][4 * q + 1] = fmaxf(pb.y + qb.y, 0.0f);
            h[1][4 * q + 2] = fmaxf(pb.z + qb.z, 0.0f);
            h[1][4 * q + 3] = fmaxf(pb.w + qb.w, 0.0f);
        }
    }

#pragma unroll 1
    for (int l = 0; l < NLAY - 1; l++) {
        float o[2][HH];
#pragma unroll
        for (int j = 0; j < HH; j++) {
            float bb = bsh[l * HH + j];
            o[0][j] = bb;
            o[1][j] = bb;
        }
        const float* Wl = Wsh + l * HH * HH;
#pragma unroll
        for (int k = 0; k < HH; k++) {
            float hA = h[0][k], hB = h[1][k];
            const float4* w4 = (const float4*)(Wl + k * HH);
#pragma unroll
            for (int j = 0; j < HH / 4; j++) {
                float4 w = w4[j];
                o[0][4 * j + 0] = fmaf(hA, w.x, o[0][4 * j + 0]);
                o[0][4 * j + 1] = fmaf(hA, w.y, o[0][4 * j + 1]);
                o[0][4 * j + 2] = fmaf(hA, w.z, o[0][4 * j + 2]);
                o[0][4 * j + 3] = fmaf(hA, w.w, o[0][4 * j + 3]);
                o[1][4 * j + 0] = fmaf(hB, w.x, o[1][4 * j + 0]);
                o[1][4 * j + 1] = fmaf(hB, w.y, o[1][4 * j + 1]);
                o[1][4 * j + 2] = fmaf(hB, w.z, o[1][4 * j + 2]);
                o[1][4 * j + 3] = fmaf(hB, w.w, o[1][4 * j + 3]);
            }
        }
#pragma unroll
        for (int j = 0; j < HH; j++) {
            h[0][j] = fmaxf(o[0][j], 0.0f);
            h[1][j] = fmaxf(o[1][j], 0.0f);
        }
    }

    float accA = bosh, accB = bosh;
#pragma unroll
    for (int k = 0; k < HH; k++) {
        float w = Wosh[k];
        accA = fmaf(h[0][k], w, accA);
        accB = fmaf(h[1][k], w, accB);
    }

    g_tmp[eA] = accA;
    atomicMax(&g_mkey[dA], fkey(accA));
    g_tmp[eB] = accB;
    atomicMax(&g_mkey[dB], fkey(accB));
}

// ---------------- fused persistent kernel: softmax + merge loop + output ----------------
__global__ void __launch_bounds__(FTPB, 4)
k_fused(const int* __restrict__ ei, float* __restrict__ out) {
    const int tid = threadIdx.x;
    const int gid0 = blockIdx.x * FTPB + tid;
    const int gstride = FGRID * FTPB;
    unsigned int bars = 0;

    // ---- phase: exp + segment sum ----
    for (int e = gid0; e < EE; e += gstride) {
        int d = ei[EE + e];
        float m = fkey_inv(g_mkey[d]);
        float ex = expf(g_tmp[e] - m);
        g_tmp[e] = ex;
        atomicAdd(&g_ssum[d], (double)ex);
    }
    gbar(++bars * FGRID);

    // ---- phase: softmax finalize + iteration-0 pack accumulation ----
    for (int e = gid0; e < EE; e += gstride) {
        int s = ei[e], d = ei[EE + e];
        float sc = g_tmp[e] / (float)g_ssum[d] + 0.5f;
        g_score[e] = sc;
        unsigned long long pk =
            ((unsigned long long)__float_as_uint(sc) << 32) | (unsigned int)(EE - e);
        atomicMax(&g_packs[s], pk);
        atomicMax(&g_packd[d], pk);
    }
    gbar(++bars * FGRID);

    // ---- merge loop ----
#pragma unroll 1
    for (int t = 0; t < MAXIT; t++) {
        bool done = iter_done(t);

        // phase A: commit pending removal; maxidx from packs; reset packs
        if (!done) {
            if (gid0 == 0) g_lc[(t + 1) & 1] = 0;
            for (int n = gid0; n < NN; n += gstride) {
                if (g_rm[n]) g_nrem[n] = 0;
                unsigned long long p0 = g_packs[n], p1 = g_packd[n];
                g_packs[n] = 0ull; g_packd[n] = 0ull;
                float ms0 = __uint_as_float((unsigned int)(p0 >> 32));
                float ms1 = __uint_as_float((unsigned int)(p1 >> 32));
                int mi = 0;
                if (ms1 > ms0) {
                    int eid = EE - (int)(unsigned int)(p1 & 0xFFFFFFFFull);
                    eid = min(eid, EE - 1);
                    mi = ei[eid];
                } else if (ms0 > ms1) {
                    int eid = EE - (int)(unsigned int)(p0 & 0xFFFFFFFFull);
                    eid = min(eid, EE - 1);
                    mi = ei[EE + eid];
                }
                g_maxidx[n] = mi;
            }
        }
        gbar(++bars * FGRID);

        // phase B: mutual-match flag + partner + survivor count
        if (!done) {
            for (int base = blockIdx.x * FTPB; base < NN; base += gstride) {
                int n = base + tid;
                int surv = 0;
                if (n < NN) {
                    int v = g_maxidx[n];
                    bool nr = g_nrem[n];
                    bool rm = nr && g_nrem[v] && (g_maxidx[v] == n);
                    g_rm[n] = rm ? 1 : 0;
                    if (rm) g_part[n] = v;
                    surv = (nr && !rm) ? 1 : 0;
                }
                unsigned m = __ballot_sync(0xffffffffu, surv);
                if ((tid & 31) == 0 && m)
                    atomicAdd(&g_cnt[t], __popc(m));
            }
        }
        gbar(++bars * FGRID);

        // phase E: compact live list + accumulate next packs
        if (!done && t != MAXIT - 1 && g_cnt[t] > THRESH) {
            int total = (t == 0) ? EE : g_lc[t & 1];
            int lane = tid & 31;
            int outp = (t + 1) & 1;
            int iters = (total + gstride - 1) / gstride;
            for (int it = 0; it < iters; it++) {
                int i = gid0 + it * gstride;
                bool inb = i < total;
                int4 rec;
                if (inb) {
                    if (t == 0) {
                        rec.x = ei[i];
                        rec.y = ei[EE + i];
                        rec.z = i;
                        rec.w = __float_as_int(g_score[i]);
                    } else {
                        rec = g_list[t & 1][i];
                    }
                }
                bool live = inb && g_nrem[rec.x] && !g_rm[rec.x]
                                && g_nrem[rec.y] && !g_rm[rec.y];
                unsigned mask = __ballot_sync(0xffffffffu, live);
                if (mask) {
                    int leader = __ffs(mask) - 1;
                    int base;
                    if (lane == leader) base = atomicAdd(&g_lc[outp], __popc(mask));
                    base = __shfl_sync(0xffffffffu, base, leader);
                    if (live) {
                        int off = __popc(mask & ((1u << lane) - 1));
                        g_list[outp][base + off] = rec;
                        unsigned long long pk =
                            ((unsigned long long)(unsigned int)rec.w << 32) |
                            (unsigned int)(EE - rec.z);
                        atomicMax(&g_packs[rec.x], pk);
                        atomicMax(&g_packd[rec.y], pk);
                    }
                }
            }
        }
        gbar(++bars * FGRID);
    }

    // ---- phase: output ----
    for (int e = gid0; e < EE; e += gstride) {
        int s = ei[e], d = ei[EE + e];
        bool live = g_nrem[s] && !g_rm[s] && g_nrem[d] && !g_rm[d];
        out[e] = live ? g_score[e] : 0.0f;
        bool removed = (g_part[s] == d) && (g_part[d] == s);
        out[EE + e] = removed ? 0.0f : 1.0f;
    }
    for (int n = gid0; n < NN; n += gstride) {
        out[2 * EE + n] = (g_nrem[n] && !g_rm[n]) ? 1.0f : 0.0f;
    }
}

extern "C" void kernel_launch(void* const* d_in, const int* in_sizes, int n_in,
                              void* d_out, int out_size) {
    const float* x  = (const float*)d_in[0];
    const int*   ei = (const int*)d_in[1];
    // d_in[2] = batch (unused, all zeros)
    const float* Wh = (const float*)d_in[3];
    const float* bh = (const float*)d_in[4];
    const float* Wo = (const float*)d_in[5];
    const float* bo = (const float*)d_in[6];
    float* out = (float*)d_out;

    const int nblocks = (NN + TPB - 1) / TPB;
    const int mblocks = (EE / 2) / MTPB;   // 6250

    k_pre<<<nblocks, TPB>>>(x, Wh, bh);
    k_mlp<<<mblocks, MTPB>>>(ei, Wh, bh, Wo, bo);
    k_fused<<<FGRID, FTPB>>>(ei, out);
}